// round 4
// baseline (speedup 1.0000x reference)
#include <cuda_runtime.h>
#include <cstdint>

// Problem dims
#define B_ 32
#define T_ 4096
#define I_ 256
#define O_ 256
#define M_ (B_ * T_)          // 131072 rows of x viewed as [M, I]
#define BTO ((size_t)B_ * T_ * O_)   // 33554432

// Scratch (device globals: no allocation allowed)
__device__ float g_S[M_ * O_];   // soma drive  [B*T, O]  (134 MB)
__device__ float g_P[M_ * O_];   // basal_mean + apical_mean  (134 MB)

// ---------------- packed f32x2 helpers (FFMA2 on sm_103a) ----------------
__device__ __forceinline__ unsigned long long pack2(float x, float y) {
    unsigned long long r;
    asm("mov.b64 %0, {%1, %2};" : "=l"(r) : "f"(x), "f"(y));
    return r;
}
__device__ __forceinline__ void unpack2(unsigned long long v, float &x, float &y) {
    asm("mov.b64 {%0, %1}, %2;" : "=f"(x), "=f"(y) : "l"(v));
}
__device__ __forceinline__ unsigned long long fma2(unsigned long long a,
                                                   unsigned long long b,
                                                   unsigned long long c) {
    unsigned long long d;
    asm("fma.rn.f32x2 %0, %1, %2, %3;" : "=l"(d) : "l"(a), "l"(b), "l"(c));
    return d;
}

// ---------------- fused 7-group GEMM ----------------
// Computes, for every row m of x:
//   g_S[m, :] = x[m] @ W_soma^T
//   g_P[m, :] = 0.25 * sum_{n<4} relu(x[m] @ W_basal[n]^T)
//             + 0.50 * sum_{n<2} relu(x[m] @ W_apical[n]^T)
// Tile: BM=128, BN=64, BK=32; 256 threads; thread tile 8x4 (4 m-pairs x 4 n).
#define BM 128
#define BN 64
#define BK 32

__global__ __launch_bounds__(256) void neurons_gemm_kernel(
    const float* __restrict__ x,
    const float* __restrict__ W_soma,
    const float* __restrict__ W_basal,
    const float* __restrict__ W_apical)
{
    __shared__ float As[BK][BM];   // x tile, transposed (k-major)
    __shared__ float Bs[BK][BN];   // weight tile, transposed

    const int tid = threadIdx.x;
    const int m0  = blockIdx.y * BM;
    const int n0  = blockIdx.x * BN;
    const int tn0 = (tid & 15) * 4;   // 0..60
    const int tm0 = (tid >> 4) * 8;   // 0..120

    float accP[8][4];
#pragma unroll
    for (int i = 0; i < 8; ++i)
#pragma unroll
        for (int j = 0; j < 4; ++j) accP[i][j] = 0.0f;

    for (int g = 0; g < 7; ++g) {
        const float* Wg;
        if (g == 0)      Wg = W_soma;
        else if (g < 5)  Wg = W_basal  + (g - 1) * (O_ * I_);
        else             Wg = W_apical + (g - 5) * (O_ * I_);
        const float scale = (g == 0) ? 0.0f : (g < 5 ? 0.25f : 0.5f);

        unsigned long long acc2[4][4];
#pragma unroll
        for (int p = 0; p < 4; ++p)
#pragma unroll
            for (int j = 0; j < 4; ++j) acc2[p][j] = 0ull;

        for (int kt = 0; kt < I_ / BK; ++kt) {
            const int kb = kt * BK;
            __syncthreads();
            // load x tile: 128 rows x 32 k = 1024 float4, 4 per thread
#pragma unroll
            for (int i = 0; i < 4; ++i) {
                int fid = tid + i * 256;
                int mm  = fid >> 3;
                int kq  = (fid & 7) * 4;
                float4 v = *reinterpret_cast<const float4*>(
                    &x[(size_t)(m0 + mm) * I_ + kb + kq]);
                As[kq + 0][mm] = v.x;
                As[kq + 1][mm] = v.y;
                As[kq + 2][mm] = v.z;
                As[kq + 3][mm] = v.w;
            }
            // load W tile: 64 rows x 32 k = 512 float4, 2 per thread
#pragma unroll
            for (int i = 0; i < 2; ++i) {
                int fid = tid + i * 256;
                int oo  = fid >> 3;
                int kq  = (fid & 7) * 4;
                float4 v = *reinterpret_cast<const float4*>(
                    &Wg[(size_t)(n0 + oo) * I_ + kb + kq]);
                Bs[kq + 0][oo] = v.x;
                Bs[kq + 1][oo] = v.y;
                Bs[kq + 2][oo] = v.z;
                Bs[kq + 3][oo] = v.w;
            }
            __syncthreads();

#pragma unroll
            for (int kk = 0; kk < BK; ++kk) {
                float4 b4 = *reinterpret_cast<const float4*>(&Bs[kk][tn0]);
                unsigned long long bb[4];
                bb[0] = pack2(b4.x, b4.x);
                bb[1] = pack2(b4.y, b4.y);
                bb[2] = pack2(b4.z, b4.z);
                bb[3] = pack2(b4.w, b4.w);
                unsigned long long ap[4];
#pragma unroll
                for (int p = 0; p < 4; ++p)
                    ap[p] = *reinterpret_cast<const unsigned long long*>(
                        &As[kk][tm0 + 2 * p]);
#pragma unroll
                for (int p = 0; p < 4; ++p)
#pragma unroll
                    for (int j = 0; j < 4; ++j)
                        acc2[p][j] = fma2(ap[p], bb[j], acc2[p][j]);
            }
        }

        // epilogue for this group
        if (g == 0) {
#pragma unroll
            for (int p = 0; p < 4; ++p) {
                float lo[4], hi[4];
#pragma unroll
                for (int j = 0; j < 4; ++j) unpack2(acc2[p][j], lo[j], hi[j]);
                size_t r0 = (size_t)(m0 + tm0 + 2 * p) * O_ + n0 + tn0;
                *reinterpret_cast<float4*>(&g_S[r0]) =
                    make_float4(lo[0], lo[1], lo[2], lo[3]);
                *reinterpret_cast<float4*>(&g_S[r0 + O_]) =
                    make_float4(hi[0], hi[1], hi[2], hi[3]);
            }
        } else {
#pragma unroll
            for (int p = 0; p < 4; ++p) {
#pragma unroll
                for (int j = 0; j < 4; ++j) {
                    float lo, hi;
                    unpack2(acc2[p][j], lo, hi);
                    accP[2 * p + 0][j] += fmaxf(lo, 0.0f) * scale;
                    accP[2 * p + 1][j] += fmaxf(hi, 0.0f) * scale;
                }
            }
        }
    }

#pragma unroll
    for (int i = 0; i < 8; ++i) {
        size_t r = (size_t)(m0 + tm0 + i) * O_ + n0 + tn0;
        *reinterpret_cast<float4*>(&g_P[r]) =
            make_float4(accP[i][0], accP[i][1], accP[i][2], accP[i][3]);
    }
}

// ---------------- sequential scan: LIF + Kuramoto ----------------
// One warp per batch, 8 neurons per lane. Mean-field reduction is pure
// intra-warp shuffles (no smem, no barriers). Identity used:
//   K * r * sin(psi - theta) = s_mean * cos(theta) - c_mean * sin(theta)
__global__ __launch_bounds__(32) void neurons_scan_kernel(
    float* __restrict__ spikes_out,
    float* __restrict__ phases_out,
    float* __restrict__ mem_out)
{
    const int b    = blockIdx.x;
    const int lane = threadIdx.x;

    const float A_MEM  = 0.95122942450071400910f;  // exp(-1/20)
    const float A_SYN  = 0.81873075307798185867f;  // exp(-1/5)
    const float A_DEND = 0.90483741803595957316f;  // exp(-1/10)
    const float OMD    = 1.0f - A_DEND;
    const float TWOPI  = 6.28318530717958647692f;
    const float OMEGA  = 62.8318530717958647692f;  // 2*pi*10
    const float INV_O  = 1.0f / 256.0f;

    float dend[8], syn[8], mem[8], th[8];
#pragma unroll
    for (int j = 0; j < 8; ++j) { dend[j] = 0.f; syn[j] = 0.f; mem[j] = 0.f; th[j] = 0.f; }

    const size_t base = ((size_t)b * T_) * O_ + lane * 8;

    // prefetch t = 0
    float4 sA = *reinterpret_cast<const float4*>(&g_S[base]);
    float4 sB = *reinterpret_cast<const float4*>(&g_S[base + 4]);
    float4 pA = *reinterpret_cast<const float4*>(&g_P[base]);
    float4 pB = *reinterpret_cast<const float4*>(&g_P[base + 4]);

    for (int t = 0; t < T_; ++t) {
        const size_t idx = base + (size_t)t * O_;

        float sv[8] = {sA.x, sA.y, sA.z, sA.w, sB.x, sB.y, sB.z, sB.w};
        float pv[8] = {pA.x, pA.y, pA.z, pA.w, pB.x, pB.y, pB.z, pB.w};

        // issue next-step loads early (independent of this step's math)
        const size_t nidx = idx + (t < T_ - 1 ? O_ : 0);
        sA = *reinterpret_cast<const float4*>(&g_S[nidx]);
        sB = *reinterpret_cast<const float4*>(&g_S[nidx + 4]);
        pA = *reinterpret_cast<const float4*>(&g_P[nidx]);
        pB = *reinterpret_cast<const float4*>(&g_P[nidx + 4]);

        float spk[8];
#pragma unroll
        for (int j = 0; j < 8; ++j) {
            dend[j] = A_DEND * dend[j] + OMD * pv[j];
            float drive = sv[j] + 0.5f * dend[j];
            syn[j] = A_SYN * syn[j] + drive;
            mem[j] = A_MEM * mem[j] + syn[j];
            float sp = (mem[j] - 1.0f > 0.0f) ? 1.0f : 0.0f;
            mem[j] -= sp;
            spk[j] = sp;
        }

        float ct[8], st[8];
#pragma unroll
        for (int j = 0; j < 8; ++j) __sincosf(th[j], &st[j], &ct[j]);

        float cs = ((ct[0] + ct[1]) + (ct[2] + ct[3])) +
                   ((ct[4] + ct[5]) + (ct[6] + ct[7]));
        float ss = ((st[0] + st[1]) + (st[2] + st[3])) +
                   ((st[4] + st[5]) + (st[6] + st[7]));
#pragma unroll
        for (int off = 16; off >= 1; off >>= 1) {
            cs += __shfl_xor_sync(0xffffffffu, cs, off);
            ss += __shfl_xor_sync(0xffffffffu, ss, off);
        }
        const float cbar = cs * INV_O;
        const float sbar = ss * INV_O;

#pragma unroll
        for (int j = 0; j < 8; ++j) {
            float dth = OMEGA + (sbar * ct[j] - cbar * st[j]) + spk[j];
            float nt  = th[j] + 0.001f * dth;
            if (nt >= TWOPI) nt -= TWOPI;
            th[j] = nt;
        }

        *reinterpret_cast<float4*>(&spikes_out[idx]) =
            make_float4(spk[0], spk[1], spk[2], spk[3]);
        *reinterpret_cast<float4*>(&spikes_out[idx + 4]) =
            make_float4(spk[4], spk[5], spk[6], spk[7]);
        *reinterpret_cast<float4*>(&phases_out[idx]) =
            make_float4(th[0], th[1], th[2], th[3]);
        *reinterpret_cast<float4*>(&phases_out[idx + 4]) =
            make_float4(th[4], th[5], th[6], th[7]);
        *reinterpret_cast<float4*>(&mem_out[idx]) =
            make_float4(mem[0], mem[1], mem[2], mem[3]);
        *reinterpret_cast<float4*>(&mem_out[idx + 4]) =
            make_float4(mem[4], mem[5], mem[6], mem[7]);
    }
}

extern "C" void kernel_launch(void* const* d_in, const int* in_sizes, int n_in,
                              void* d_out, int out_size) {
    const float* x        = (const float*)d_in[0];  // [B,T,I]
    const float* W_soma   = (const float*)d_in[1];  // [O,I]
    const float* W_basal  = (const float*)d_in[2];  // [4,O,I]
    const float* W_apical = (const float*)d_in[3];  // [2,O,I]

    float* spikes = (float*)d_out;          // [B,T,O]
    float* phases = spikes + BTO;           // [B,T,O]
    float* mems   = phases + BTO;           // [B,T,O]

    dim3 grid(O_ / BN, M_ / BM);            // (4, 1024)
    neurons_gemm_kernel<<<grid, 256>>>(x, W_soma, W_basal, W_apical);
    neurons_scan_kernel<<<B_, 32>>>(spikes, phases, mems);
}

// round 8
// speedup vs baseline: 1.1655x; 1.1655x over previous
#include <cuda_runtime.h>
#include <cstdint>

// Problem dims
#define B_ 32
#define T_ 4096
#define I_ 256
#define O_ 256
#define M_ (B_ * T_)                 // 131072
#define BTO ((size_t)B_ * T_ * O_)   // 33554432

// Scratch (device globals: no allocation allowed)
__device__ float g_S[M_ * O_];   // soma drive  [B*T, O]
__device__ float g_P[M_ * O_];   // basal_mean + apical_mean

// ---------------- packed f32x2 helpers (FFMA2 on sm_103a) ----------------
__device__ __forceinline__ unsigned long long pack2(float x, float y) {
    unsigned long long r;
    asm("mov.b64 %0, {%1, %2};" : "=l"(r) : "f"(x), "f"(y));
    return r;
}
__device__ __forceinline__ void unpack2(unsigned long long v, float &x, float &y) {
    asm("mov.b64 {%0, %1}, %2;" : "=f"(x), "=f"(y) : "l"(v));
}
__device__ __forceinline__ unsigned long long fma2(unsigned long long a,
                                                   unsigned long long b,
                                                   unsigned long long c) {
    unsigned long long d;
    asm("fma.rn.f32x2 %0, %1, %2, %3;" : "=l"(d) : "l"(a), "l"(b), "l"(c));
    return d;
}

// ---------------- fused 7-group GEMM (validated in R7: output0 == R4) ------
// Block: BM=64 rows of x, full O=256 columns. x tile (64 x 256) resident in
// smem for ALL 7 groups (loaded once). W tiles double-buffered.
// Thread tile: 8m x 8n (4 n-pairs strided by 64 for conflict-free LDS.64).
#define BM 64
#define BK 32
#define AS_LD 68                      // padded row stride (floats), 16B-aligned rows
#define BS_LD 258                     // padded row stride (floats), 8B-aligned rows
#define AS_FLOATS (I_ * AS_LD)        // 17408
#define BS_FLOATS (BK * BS_LD)        // 8256
#define SMEM_BYTES ((AS_FLOATS + 2 * BS_FLOATS) * 4)   // 135680

__device__ __forceinline__ void ldW(float4 (&r)[8], const float* __restrict__ Wg,
                                    int kb, int tid) {
#pragma unroll
    for (int i = 0; i < 8; ++i) {
        int fid = tid + i * 256;
        int oo  = fid >> 3;
        int kq  = (fid & 7) * 4;
        r[i] = *reinterpret_cast<const float4*>(&Wg[(size_t)oo * I_ + kb + kq]);
    }
}
__device__ __forceinline__ void stsW(float* __restrict__ Bs, const float4 (&r)[8],
                                     int tid) {
#pragma unroll
    for (int i = 0; i < 8; ++i) {
        int fid = tid + i * 256;
        int oo  = fid >> 3;
        int kq  = (fid & 7) * 4;
        Bs[(kq + 0) * BS_LD + oo] = r[i].x;
        Bs[(kq + 1) * BS_LD + oo] = r[i].y;
        Bs[(kq + 2) * BS_LD + oo] = r[i].z;
        Bs[(kq + 3) * BS_LD + oo] = r[i].w;
    }
}

extern __shared__ float smem_dyn[];

__global__ __launch_bounds__(256, 1) void neurons_gemm_kernel(
    const float* __restrict__ x,
    const float* __restrict__ W_soma,
    const float* __restrict__ W_basal,
    const float* __restrict__ W_apical)
{
    float* As  = smem_dyn;                     // [256][AS_LD] : As[k][m]
    float* Bsb = smem_dyn + AS_FLOATS;         // 2 x [32][BS_LD] : Bs[k][n]

    const int tid = threadIdx.x;
    const int tx  = tid & 31;       // n-group: pairs at tx*2 + 64*j
    const int ty  = tid >> 5;       // m-group: rows ty*8 .. ty*8+7
    const int m0  = blockIdx.x * BM;

    // ---- load x tile once: conflict-free transposed store ----
#pragma unroll
    for (int i = 0; i < 16; ++i) {
        int fid = tid + i * 256;
        int mm  = fid & 63;
        int kq  = (fid >> 6) * 4;
        float4 v = *reinterpret_cast<const float4*>(&x[(size_t)(m0 + mm) * I_ + kq]);
        As[(kq + 0) * AS_LD + mm] = v.x;
        As[(kq + 1) * AS_LD + mm] = v.y;
        As[(kq + 2) * AS_LD + mm] = v.z;
        As[(kq + 3) * AS_LD + mm] = v.w;
    }

    float accP[8][8];
#pragma unroll
    for (int i = 0; i < 8; ++i)
#pragma unroll
        for (int j = 0; j < 8; ++j) accP[i][j] = 0.0f;

    float4 r[8];

    for (int g = 0; g < 7; ++g) {
        const float* Wg;
        if (g == 0)      Wg = W_soma;
        else if (g < 5)  Wg = W_basal  + (size_t)(g - 1) * (O_ * I_);
        else             Wg = W_apical + (size_t)(g - 5) * (O_ * I_);
        const float scale = (g < 5) ? 0.25f : 0.5f;

        unsigned long long acc2[8][4];
#pragma unroll
        for (int mi = 0; mi < 8; ++mi)
#pragma unroll
            for (int j = 0; j < 4; ++j) acc2[mi][j] = 0ull;

        __syncthreads();                 // As ready (g=0) / Bs free (g>0)
        ldW(r, Wg, 0, tid);
        stsW(Bsb, r, tid);

        for (int kt = 0; kt < I_ / BK; ++kt) {
            __syncthreads();
            if (kt < 7) ldW(r, Wg, (kt + 1) * BK, tid);

            const float* Bc = Bsb + (kt & 1) * BS_FLOATS;
            const float* Ac = As + (size_t)(kt * BK) * AS_LD + ty * 8;

#pragma unroll 8
            for (int kk = 0; kk < BK; ++kk) {
                float4 a0 = *reinterpret_cast<const float4*>(&Ac[kk * AS_LD]);
                float4 a1 = *reinterpret_cast<const float4*>(&Ac[kk * AS_LD + 4]);
                unsigned long long aa[8];
                aa[0] = pack2(a0.x, a0.x); aa[1] = pack2(a0.y, a0.y);
                aa[2] = pack2(a0.z, a0.z); aa[3] = pack2(a0.w, a0.w);
                aa[4] = pack2(a1.x, a1.x); aa[5] = pack2(a1.y, a1.y);
                aa[6] = pack2(a1.z, a1.z); aa[7] = pack2(a1.w, a1.w);
                unsigned long long bb[4];
#pragma unroll
                for (int j = 0; j < 4; ++j)
                    bb[j] = *reinterpret_cast<const unsigned long long*>(
                        &Bc[kk * BS_LD + tx * 2 + j * 64]);
#pragma unroll
                for (int mi = 0; mi < 8; ++mi)
#pragma unroll
                    for (int j = 0; j < 4; ++j)
                        acc2[mi][j] = fma2(aa[mi], bb[j], acc2[mi][j]);
            }

            if (kt < 7) stsW(Bsb + ((kt + 1) & 1) * BS_FLOATS, r, tid);
        }

        if (g == 0) {
#pragma unroll
            for (int mi = 0; mi < 8; ++mi) {
                size_t row = (size_t)(m0 + ty * 8 + mi) * O_;
#pragma unroll
                for (int j = 0; j < 4; ++j) {
                    float lo, hi;
                    unpack2(acc2[mi][j], lo, hi);
                    *reinterpret_cast<float2*>(&g_S[row + tx * 2 + j * 64]) =
                        make_float2(lo, hi);
                }
            }
        } else {
#pragma unroll
            for (int mi = 0; mi < 8; ++mi)
#pragma unroll
                for (int j = 0; j < 4; ++j) {
                    float lo, hi;
                    unpack2(acc2[mi][j], lo, hi);
                    accP[mi][2 * j + 0] += fmaxf(lo, 0.0f) * scale;
                    accP[mi][2 * j + 1] += fmaxf(hi, 0.0f) * scale;
                }
        }
    }

#pragma unroll
    for (int mi = 0; mi < 8; ++mi) {
        size_t row = (size_t)(m0 + ty * 8 + mi) * O_;
#pragma unroll
        for (int j = 0; j < 4; ++j)
            *reinterpret_cast<float2*>(&g_P[row + tx * 2 + j * 64]) =
                make_float2(accP[mi][2 * j], accP[mi][2 * j + 1]);
    }
}

// ---------------- sequential scan: LIF + Kuramoto (R4 exact formulation) ---
// One warp per batch, 8 neurons per lane. Mean-field reduction is pure
// intra-warp shuffles. Identity used (exact trig identity):
//   K * r * sin(psi - theta) = s_mean * cos(theta) - c_mean * sin(theta)
// sincos is evaluated EXACTLY at the current theta every step (no
// extrapolation tricks — the phase dynamics amplify formulation drift).
__global__ __launch_bounds__(32) void neurons_scan_kernel(
    float* __restrict__ spikes_out,
    float* __restrict__ phases_out,
    float* __restrict__ mem_out)
{
    const int b    = blockIdx.x;
    const int lane = threadIdx.x;

    const float A_MEM  = 0.95122942450071400910f;  // exp(-1/20)
    const float A_SYN  = 0.81873075307798185867f;  // exp(-1/5)
    const float A_DEND = 0.90483741803595957316f;  // exp(-1/10)
    const float OMD    = 1.0f - A_DEND;
    const float TWOPI  = 6.28318530717958647692f;
    const float OMEGA  = 62.8318530717958647692f;  // 2*pi*10
    const float INV_O  = 1.0f / 256.0f;

    float dend[8], syn[8], mem[8], th[8];
#pragma unroll
    for (int j = 0; j < 8; ++j) { dend[j] = 0.f; syn[j] = 0.f; mem[j] = 0.f; th[j] = 0.f; }

    const size_t base = ((size_t)b * T_) * O_ + lane * 8;

    // prefetch t = 0
    float4 sA = *reinterpret_cast<const float4*>(&g_S[base]);
    float4 sB = *reinterpret_cast<const float4*>(&g_S[base + 4]);
    float4 pA = *reinterpret_cast<const float4*>(&g_P[base]);
    float4 pB = *reinterpret_cast<const float4*>(&g_P[base + 4]);

    for (int t = 0; t < T_; ++t) {
        const size_t idx = base + (size_t)t * O_;

        float sv[8] = {sA.x, sA.y, sA.z, sA.w, sB.x, sB.y, sB.z, sB.w};
        float pv[8] = {pA.x, pA.y, pA.z, pA.w, pB.x, pB.y, pB.z, pB.w};

        // issue next-step loads early (independent of this step's math)
        const size_t nidx = idx + (t < T_ - 1 ? O_ : 0);
        sA = *reinterpret_cast<const float4*>(&g_S[nidx]);
        sB = *reinterpret_cast<const float4*>(&g_S[nidx + 4]);
        pA = *reinterpret_cast<const float4*>(&g_P[nidx]);
        pB = *reinterpret_cast<const float4*>(&g_P[nidx + 4]);

        float spk[8];
#pragma unroll
        for (int j = 0; j < 8; ++j) {
            dend[j] = A_DEND * dend[j] + OMD * pv[j];
            float drive = sv[j] + 0.5f * dend[j];
            syn[j] = A_SYN * syn[j] + drive;
            mem[j] = A_MEM * mem[j] + syn[j];
            float sp = (mem[j] - 1.0f > 0.0f) ? 1.0f : 0.0f;
            mem[j] -= sp;
            spk[j] = sp;
        }

        float ct[8], st[8];
#pragma unroll
        for (int j = 0; j < 8; ++j) __sincosf(th[j], &st[j], &ct[j]);

        float cs = ((ct[0] + ct[1]) + (ct[2] + ct[3])) +
                   ((ct[4] + ct[5]) + (ct[6] + ct[7]));
        float ss = ((st[0] + st[1]) + (st[2] + st[3])) +
                   ((st[4] + st[5]) + (st[6] + st[7]));
#pragma unroll
        for (int off = 16; off >= 1; off >>= 1) {
            cs += __shfl_xor_sync(0xffffffffu, cs, off);
            ss += __shfl_xor_sync(0xffffffffu, ss, off);
        }
        const float cbar = cs * INV_O;
        const float sbar = ss * INV_O;

#pragma unroll
        for (int j = 0; j < 8; ++j) {
            float dth = OMEGA + (sbar * ct[j] - cbar * st[j]) + spk[j];
            float nt  = th[j] + 0.001f * dth;
            if (nt >= TWOPI) nt -= TWOPI;
            th[j] = nt;
        }

        *reinterpret_cast<float4*>(&spikes_out[idx]) =
            make_float4(spk[0], spk[1], spk[2], spk[3]);
        *reinterpret_cast<float4*>(&spikes_out[idx + 4]) =
            make_float4(spk[4], spk[5], spk[6], spk[7]);
        *reinterpret_cast<float4*>(&phases_out[idx]) =
            make_float4(th[0], th[1], th[2], th[3]);
        *reinterpret_cast<float4*>(&phases_out[idx + 4]) =
            make_float4(th[4], th[5], th[6], th[7]);
        *reinterpret_cast<float4*>(&mem_out[idx]) =
            make_float4(mem[0], mem[1], mem[2], mem[3]);
        *reinterpret_cast<float4*>(&mem_out[idx + 4]) =
            make_float4(mem[4], mem[5], mem[6], mem[7]);
    }
}

extern "C" void kernel_launch(void* const* d_in, const int* in_sizes, int n_in,
                              void* d_out, int out_size) {
    const float* x        = (const float*)d_in[0];  // [B,T,I]
    const float* W_soma   = (const float*)d_in[1];  // [O,I]
    const float* W_basal  = (const float*)d_in[2];  // [4,O,I]
    const float* W_apical = (const float*)d_in[3];  // [2,O,I]

    float* spikes = (float*)d_out;          // [B,T,O]
    float* phases = spikes + BTO;           // [B,T,O]
    float* mems   = phases + BTO;           // [B,T,O]

    (void)cudaFuncSetAttribute(neurons_gemm_kernel,
                               cudaFuncAttributeMaxDynamicSharedMemorySize,
                               SMEM_BYTES);

    neurons_gemm_kernel<<<M_ / BM, 256, SMEM_BYTES>>>(x, W_soma, W_basal, W_apical);
    neurons_scan_kernel<<<B_, 32>>>(spikes, phases, mems);
}